// round 7
// baseline (speedup 1.0000x reference)
#include <cuda_runtime.h>
#include <cstdint>
#include <math_constants.h>

// Problem constants
#define BB   16
#define PP   196
#define DD   512
#define LL   32
#define HID  512
#define AA   512
#define MM   (BB*LL)
#define PCN  7
#define PCL  28

// ---------------- scratch (device globals; no allocation allowed) -----------
__device__ __align__(16) float g_hlin[MM * AA];
__device__ __align__(16) float g_scores[MM * PP];
__device__ __align__(16) float g_attn[MM * PP];
__device__ __align__(16) float g_ctx[MM * DD];
__device__ __align__(16) float g_part[PCN * MM * DD];

// ===================== tf32 helpers (sm_80+ features only) ===================
__device__ __forceinline__ uint32_t f2tf(float x) {
    uint32_t r;
    asm("cvt.rna.tf32.f32 %0, %1;" : "=r"(r) : "f"(x));
    return r;
}
__device__ __forceinline__ void mma8(float* c,
    uint32_t a0, uint32_t a1, uint32_t a2, uint32_t a3,
    uint32_t b0, uint32_t b1)
{
    asm volatile(
        "mma.sync.aligned.m16n8k8.row.col.f32.tf32.tf32.f32 "
        "{%0,%1,%2,%3}, {%4,%5,%6,%7}, {%8,%9}, {%0,%1,%2,%3};"
        : "+f"(c[0]), "+f"(c[1]), "+f"(c[2]), "+f"(c[3])
        : "r"(a0), "r"(a1), "r"(a2), "r"(a3), "r"(b0), "r"(b1));
}

// ===================== tf32x3 mma.sync NT GEMM ===============================
// out[m,n] = sum_k X[m,k]*Wt[n,k] + bias[n]   (MODE1: X=g_ctx, *mul, out=outp)
// BM=64, BN=32, BK=16. 8 warps = 4(m) x 2(n), warp tile 16x16.
// Smem holds hi/lo tf32 packed per fragment-pair:
//   slot[g*4+t] = {hi[8g+t], hi[8g+t+4], lo[8g+t], lo[8g+t+4]}   (float4)
// Row stride 12 float4 -> (4r+t) mod 8 distinct per LDS.128 phase (no conflicts).
// Double-buffered, register-prefetch pipeline. grid = (16, 8) = 128 blocks.
template<int MODE>
__global__ __launch_bounds__(256) void gemm_mma(
    const float* __restrict__ Xp, const float* __restrict__ Wt,
    const float* __restrict__ bias, const float* __restrict__ mul,
    float* __restrict__ outp)
{
    __shared__ float4 Xs[2][64][12];
    __shared__ float4 Ws[2][32][12];

    const int tid  = threadIdx.x;
    const int wid  = tid >> 5;
    const int lane = tid & 31;
    const int wm   = wid & 3;        // 0..3 -> m
    const int wn   = wid >> 2;       // 0..1 -> n
    const int bm   = blockIdx.y * 64;
    const int bn   = blockIdx.x * 32;

    const float* X = (MODE == 0) ? Xp : g_ctx;

    // loader mapping: 64 rows x 16 k; thread -> (row, quarter)
    const int xrow = tid >> 2;            // 0..63
    const int tq   = tid & 3;             // quarter: k = tq*4 .. tq*4+3
    const int pos  = tq & 1;              // hi-pair slot component (0 or 1)
    const int gg   = tq >> 1;             // k8 group (0 or 1)
    const int wrow = (tid & 127) >> 2;    // 0..31 (threads 0..127 only)

    const float* xg = X  + (size_t)(bm + xrow) * 512 + tq * 4;
    const float* wg = Wt + (size_t)(bn + wrow) * 512 + tq * 4;

    float acc[2][4];
#pragma unroll
    for (int j = 0; j < 2; ++j)
#pragma unroll
        for (int i = 0; i < 4; ++i) acc[j][i] = 0.f;

    float4 xv = *(const float4*)xg;
    float4 wv;
    if (tid < 128) wv = *(const float4*)wg;

    // store chunk 0 -> buf 0
    {
        float* bx = (float*)&Xs[0][xrow][gg * 4];
        const float xe[4] = {xv.x, xv.y, xv.z, xv.w};
#pragma unroll
        for (int e = 0; e < 4; ++e) {
            uint32_t h = f2tf(xe[e]);
            uint32_t l = f2tf(xe[e] - __uint_as_float(h));
            bx[e * 4 + pos]     = __uint_as_float(h);
            bx[e * 4 + 2 + pos] = __uint_as_float(l);
        }
        if (tid < 128) {
            float* bw = (float*)&Ws[0][wrow][gg * 4];
            const float we[4] = {wv.x, wv.y, wv.z, wv.w};
#pragma unroll
            for (int e = 0; e < 4; ++e) {
                uint32_t h = f2tf(we[e]);
                uint32_t l = f2tf(we[e] - __uint_as_float(h));
                bw[e * 4 + pos]     = __uint_as_float(h);
                bw[e * 4 + 2 + pos] = __uint_as_float(l);
            }
        }
    }
    __syncthreads();

    const int ar0 = wm * 16 + (lane >> 2);     // A row (first of pair)
    const int tfrag = lane & 3;

#pragma unroll 1
    for (int c = 0; c < 32; ++c) {
        // prefetch chunk c+1
        if (c < 31) {
            xv = *(const float4*)(xg + (c + 1) * 16);
            if (tid < 128) wv = *(const float4*)(wg + (c + 1) * 16);
        }

        const int cur = c & 1;
#pragma unroll
        for (int g = 0; g < 2; ++g) {
            float4 pa0 = Xs[cur][ar0][g * 4 + tfrag];
            float4 pa1 = Xs[cur][ar0 + 8][g * 4 + tfrag];
            uint32_t a0h = __float_as_uint(pa0.x), a2h = __float_as_uint(pa0.y);
            uint32_t a0l = __float_as_uint(pa0.z), a2l = __float_as_uint(pa0.w);
            uint32_t a1h = __float_as_uint(pa1.x), a3h = __float_as_uint(pa1.y);
            uint32_t a1l = __float_as_uint(pa1.z), a3l = __float_as_uint(pa1.w);
#pragma unroll
            for (int j = 0; j < 2; ++j) {
                const int n0 = wn * 16 + j * 8 + (lane >> 2);
                float4 pb = Ws[cur][n0][g * 4 + tfrag];
                uint32_t b0h = __float_as_uint(pb.x), b1h = __float_as_uint(pb.y);
                uint32_t b0l = __float_as_uint(pb.z), b1l = __float_as_uint(pb.w);
                mma8(acc[j], a0h, a1h, a2h, a3h, b0h, b1h);
                mma8(acc[j], a0h, a1h, a2h, a3h, b0l, b1l);
                mma8(acc[j], a0l, a1l, a2l, a3l, b0h, b1h);
            }
        }

        if (c < 31) {
            const int nxt = cur ^ 1;
            float* bx = (float*)&Xs[nxt][xrow][gg * 4];
            const float xe[4] = {xv.x, xv.y, xv.z, xv.w};
#pragma unroll
            for (int e = 0; e < 4; ++e) {
                uint32_t h = f2tf(xe[e]);
                uint32_t l = f2tf(xe[e] - __uint_as_float(h));
                bx[e * 4 + pos]     = __uint_as_float(h);
                bx[e * 4 + 2 + pos] = __uint_as_float(l);
            }
            if (tid < 128) {
                float* bw = (float*)&Ws[nxt][wrow][gg * 4];
                const float we[4] = {wv.x, wv.y, wv.z, wv.w};
#pragma unroll
                for (int e = 0; e < 4; ++e) {
                    uint32_t h = f2tf(we[e]);
                    uint32_t l = f2tf(we[e] - __uint_as_float(h));
                    bw[e * 4 + pos]     = __uint_as_float(h);
                    bw[e * 4 + 2 + pos] = __uint_as_float(l);
                }
            }
            __syncthreads();
        }
    }

    // epilogue: c0->[m0][n], c1->[m0][n+1], c2->[m1][n], c3->[m1][n+1]
    float* out = (MODE == 0) ? g_hlin : outp;
    const int m0 = bm + wm * 16 + (lane >> 2);
    const int m1 = m0 + 8;
    const int t2 = (lane & 3) * 2;
#pragma unroll
    for (int j = 0; j < 2; ++j) {
        const int n = bn + wn * 16 + j * 8 + t2;
        const float bi0 = bias[n], bi1 = bias[n + 1];
        float v0 = acc[j][0] + bi0, v1 = acc[j][1] + bi1;
        float v2 = acc[j][2] + bi0, v3 = acc[j][3] + bi1;
        if (MODE == 1) {
            float2 h0 = *(const float2*)&mul[(size_t)m0 * 512 + n];
            float2 h1 = *(const float2*)&mul[(size_t)m1 * 512 + n];
            v0 *= h0.x; v1 *= h0.y; v2 *= h1.x; v3 *= h1.y;
        }
        *(float2*)&out[(size_t)m0 * 512 + n] = make_float2(v0, v1);
        *(float2*)&out[(size_t)m1 * 512 + n] = make_float2(v2, v3);
    }
}

// ===================== scores / softmax / ctx (SIMT) =========================
__global__ __launch_bounds__(256) void scores_kernel(
    const float* __restrict__ fmaps, const float* __restrict__ wrect)
{
    const int b  = blockIdx.y;
    const int pt = blockIdx.x;
    __shared__ float4 fs4[14 * 128];
    const float4* fbase = (const float4*)(fmaps + (size_t)(b * PP + pt * 14) * DD);
    for (int i = threadIdx.x; i < 14 * 128; i += 256) fs4[i] = fbase[i];
    __syncthreads();

    const int w = threadIdx.x >> 5, lane = threadIdx.x & 31;
    float wr[4][4];
#pragma unroll
    for (int j = 0; j < 4; ++j) {
        float4 v = ((const float4*)wrect)[j * 32 + lane];
        wr[j][0] = v.x; wr[j][1] = v.y; wr[j][2] = v.z; wr[j][3] = v.w;
    }
#pragma unroll
    for (int lg = 0; lg < 4; ++lg) {
        const int l = lg * 8 + w;
        float g[4][4];
        const float4* gp = (const float4*)(g_hlin + (size_t)(b * LL + l) * AA);
#pragma unroll
        for (int j = 0; j < 4; ++j) {
            float4 v = gp[j * 32 + lane];
            g[j][0] = v.x; g[j][1] = v.y; g[j][2] = v.z; g[j][3] = v.w;
        }
        for (int p = 0; p < 14; ++p) {
            float acc = 0.f;
#pragma unroll
            for (int j = 0; j < 4; ++j) {
                float4 f = fs4[p * 128 + j * 32 + lane];
                acc = fmaf(fmaxf(f.x + g[j][0], 0.f), wr[j][0], acc);
                acc = fmaf(fmaxf(f.y + g[j][1], 0.f), wr[j][1], acc);
                acc = fmaf(fmaxf(f.z + g[j][2], 0.f), wr[j][2], acc);
                acc = fmaf(fmaxf(f.w + g[j][3], 0.f), wr[j][3], acc);
            }
#pragma unroll
            for (int o = 16; o; o >>= 1)
                acc += __shfl_xor_sync(0xffffffffu, acc, o);
            if (lane == 0)
                g_scores[(size_t)(b * LL + l) * PP + pt * 14 + p] = acc;
        }
    }
}

__global__ __launch_bounds__(256) void softmax_kernel(float* __restrict__ attn_out)
{
    const int row = blockIdx.x, tid = threadIdx.x;
    const int lane = tid & 31, wid = tid >> 5;
    __shared__ float redm[8], reds[8];

    float v = -CUDART_INF_F;
    if (tid < PP) v = g_scores[(size_t)row * PP + tid];
    float m = v;
#pragma unroll
    for (int o = 16; o; o >>= 1) m = fmaxf(m, __shfl_xor_sync(0xffffffffu, m, o));
    if (lane == 0) redm[wid] = m;
    __syncthreads();
    float bm = redm[0];
#pragma unroll
    for (int i = 1; i < 8; ++i) bm = fmaxf(bm, redm[i]);

    float e = (tid < PP) ? __expf(v - bm) : 0.f;
    float s = e;
#pragma unroll
    for (int o = 16; o; o >>= 1) s += __shfl_xor_sync(0xffffffffu, s, o);
    if (lane == 0) reds[wid] = s;
    __syncthreads();
    float bs = 0.f;
#pragma unroll
    for (int i = 0; i < 8; ++i) bs += reds[i];
    float inv = 1.f / bs;

    if (tid < PP) {
        float a = e * inv;
        g_attn[(size_t)row * PP + tid] = a;
        if (attn_out) attn_out[(size_t)row * PP + tid] = a;
    }
}

__global__ __launch_bounds__(256) void ctx_part_kernel(const float* __restrict__ fmaps)
{
    const int b  = blockIdx.y;
    const int pc = blockIdx.z;
    const int dbase = blockIdx.x * 128 + (threadIdx.x & 31) * 4;
    const int lg = threadIdx.x >> 5;

    __shared__ float at_s[LL * PCL];
    const float* ab = g_attn + (size_t)b * LL * PP + pc * PCL;
    for (int i = threadIdx.x; i < LL * PCL; i += 256) {
        int l = i / PCL, j = i - l * PCL;
        at_s[i] = ab[(size_t)l * PP + j];
    }
    __syncthreads();

    float acc[4][4];
#pragma unroll
    for (int i = 0; i < 4; ++i)
#pragma unroll
        for (int k = 0; k < 4; ++k) acc[i][k] = 0.f;

    const float* fp = fmaps + ((size_t)b * PP + pc * PCL) * DD + dbase;
#pragma unroll
    for (int j0 = 0; j0 < PCL; j0 += 7) {
        float4 f[7];
#pragma unroll
        for (int t = 0; t < 7; ++t)
            f[t] = *(const float4*)&fp[(size_t)(j0 + t) * DD];
#pragma unroll
        for (int t = 0; t < 7; ++t) {
#pragma unroll
            for (int i = 0; i < 4; ++i) {
                float a = at_s[(lg * 4 + i) * PCL + j0 + t];
                acc[i][0] = fmaf(a, f[t].x, acc[i][0]);
                acc[i][1] = fmaf(a, f[t].y, acc[i][1]);
                acc[i][2] = fmaf(a, f[t].z, acc[i][2]);
                acc[i][3] = fmaf(a, f[t].w, acc[i][3]);
            }
        }
    }
#pragma unroll
    for (int i = 0; i < 4; ++i) {
        int l = lg * 4 + i;
        *(float4*)&g_part[((size_t)pc * MM + b * LL + l) * DD + dbase] =
            make_float4(acc[i][0], acc[i][1], acc[i][2], acc[i][3]);
    }
}

__global__ __launch_bounds__(256) void ctx_reduce_kernel()
{
    const int i = blockIdx.x * 256 + threadIdx.x;   // float4 idx < 65536
    const float4* p = (const float4*)g_part;
    float4 s = p[i];
#pragma unroll
    for (int pc = 1; pc < PCN; ++pc) {
        float4 v = p[(size_t)pc * (MM * DD / 4) + i];
        s.x += v.x; s.y += v.y; s.z += v.z; s.w += v.w;
    }
    ((float4*)g_ctx)[i] = s;
}

// ---------------------------------------------------------------------------
extern "C" void kernel_launch(void* const* d_in, const int* in_sizes, int n_in,
                              void* d_out, int out_size)
{
    const float* maps     = (const float*)d_in[0];
    const float* hiddens  = (const float*)d_in[1];
    const float* W_hidden = (const float*)d_in[2];
    const float* b_hidden = (const float*)d_in[3];
    const float* W_rect   = (const float*)d_in[4];
    // d_in[5] = b_rect: softmax-invariant, unused
    const float* W_co     = (const float*)d_in[6];
    const float* b_co     = (const float*)d_in[7];

    float* out_co = (float*)d_out;
    float* out_attn = nullptr;
    if (out_size >= MM * HID + MM * PP)
        out_attn = out_co + MM * HID;

    // 1) hlin = hiddens @ W_hidden^T + b_hidden   -> g_hlin  (tf32x3 mma.sync)
    gemm_mma<0><<<dim3(16, 8), 256>>>(hiddens, W_hidden, b_hidden,
                                      nullptr, nullptr);
    // 2) additive co-attention scores             -> g_scores
    scores_kernel<<<dim3(14, BB), 256>>>(maps, W_rect);
    // 3) softmax over pixels                      -> g_attn (+ d_out tail)
    softmax_kernel<<<MM, 256>>>(out_attn);
    // 4a) ctx partials over 7 p-chunks            -> g_part
    ctx_part_kernel<<<dim3(4, BB, PCN), 256>>>(maps);
    // 4b) deterministic reduce                    -> g_ctx
    ctx_reduce_kernel<<<256, 256>>>();
    // 5) co_att = (ctx @ W_co^T + b_co) * hiddens -> d_out head (tf32x3)
    gemm_mma<1><<<dim3(16, 8), 256>>>(nullptr, W_co, b_co,
                                      hiddens, out_co);
}

// round 9
// speedup vs baseline: 1.5483x; 1.5483x over previous
#include <cuda_runtime.h>
#include <cstdint>
#include <math_constants.h>

// Problem constants
#define BB   16
#define PP   196
#define DD   512
#define LL   32
#define HID  512
#define AA   512
#define MM   (BB*LL)
#define PT   7            // pixels per scores tile
#define KC   14           // ctx k-chunk (14*14 = 196)

// ---------------- scratch (device globals; no allocation allowed) -----------
__device__ __align__(16) float g_hlin[MM * AA];
__device__ __align__(16) float g_scores[MM * PP];
__device__ __align__(16) float g_attnT[BB * PP * LL];   // [b][p][l]
__device__ __align__(16) float g_ctx[MM * DD];

// ---------------------------------------------------------------------------
// NT SGEMM  out[m,n] = sum_k X[m,k] * Wt[n,k] + bias[n]
//   MODE 0: X = Xp param, out = g_hlin
//   MODE 1: X = g_ctx, out = outp * mul
// BM=64, BN=32, BK=32, 256 threads (16x16). K-major double-buffered smem,
// register-prefetch pipeline. grid = (16, 8) = 128 blocks.
// ---------------------------------------------------------------------------
template<int MODE>
__global__ __launch_bounds__(256) void gemm_nt_kernel(
    const float* __restrict__ Xp, const float* __restrict__ Wt,
    const float* __restrict__ bias, const float* __restrict__ mul,
    float* __restrict__ outp)
{
    __shared__ __align__(16) float Xs[2][32][68];
    __shared__ __align__(16) float Ws[2][32][34];

    const int tid = threadIdx.x;
    const int tx = tid & 15;         // N
    const int ty = tid >> 4;         // M
    const int bm = blockIdx.y * 64;
    const int bn = blockIdx.x * 32;

    float acc[4][2];
#pragma unroll
    for (int i = 0; i < 4; ++i)
#pragma unroll
        for (int j = 0; j < 2; ++j) acc[i][j] = 0.f;

    const int xrow = tid >> 2;             // 0..63
    const int xko  = (tid & 3) * 4;        // 0,4,8,12 ; second vec at +16
    const int wrow = tid >> 3;             // 0..31
    const int wko  = (tid & 7) * 4;        // 0..28

    const float* X = (MODE == 0) ? Xp : g_ctx;
    const float* xg0 = X + (size_t)(bm + xrow) * 512 + xko;
    const float* wg  = Wt + (size_t)(bn + wrow) * 512 + wko;

    float4 xv0 = *(const float4*)(xg0);
    float4 xv1 = *(const float4*)(xg0 + 16);
    float4 wv  = *(const float4*)(wg);

    Xs[0][xko + 0][xrow] = xv0.x; Xs[0][xko + 1][xrow] = xv0.y;
    Xs[0][xko + 2][xrow] = xv0.z; Xs[0][xko + 3][xrow] = xv0.w;
    Xs[0][xko + 16][xrow] = xv1.x; Xs[0][xko + 17][xrow] = xv1.y;
    Xs[0][xko + 18][xrow] = xv1.z; Xs[0][xko + 19][xrow] = xv1.w;
    Ws[0][wko + 0][wrow] = wv.x; Ws[0][wko + 1][wrow] = wv.y;
    Ws[0][wko + 2][wrow] = wv.z; Ws[0][wko + 3][wrow] = wv.w;
    __syncthreads();

#pragma unroll 1
    for (int c = 0; c < 16; ++c) {
        if (c < 15) {
            const float* xg = xg0 + (c + 1) * 32;
            xv0 = *(const float4*)(xg);
            xv1 = *(const float4*)(xg + 16);
            wv  = *(const float4*)(wg + (c + 1) * 32);
        }

        const int cur = c & 1;
#pragma unroll
        for (int kk = 0; kk < 32; ++kk) {
            float4 a = *(const float4*)&Xs[cur][kk][ty * 4];
            float2 bv = *(const float2*)&Ws[cur][kk][tx * 2];
            acc[0][0] = fmaf(a.x, bv.x, acc[0][0]); acc[0][1] = fmaf(a.x, bv.y, acc[0][1]);
            acc[1][0] = fmaf(a.y, bv.x, acc[1][0]); acc[1][1] = fmaf(a.y, bv.y, acc[1][1]);
            acc[2][0] = fmaf(a.z, bv.x, acc[2][0]); acc[2][1] = fmaf(a.z, bv.y, acc[2][1]);
            acc[3][0] = fmaf(a.w, bv.x, acc[3][0]); acc[3][1] = fmaf(a.w, bv.y, acc[3][1]);
        }

        if (c < 15) {
            const int nxt = cur ^ 1;
            Xs[nxt][xko + 0][xrow] = xv0.x; Xs[nxt][xko + 1][xrow] = xv0.y;
            Xs[nxt][xko + 2][xrow] = xv0.z; Xs[nxt][xko + 3][xrow] = xv0.w;
            Xs[nxt][xko + 16][xrow] = xv1.x; Xs[nxt][xko + 17][xrow] = xv1.y;
            Xs[nxt][xko + 18][xrow] = xv1.z; Xs[nxt][xko + 19][xrow] = xv1.w;
            Ws[nxt][wko + 0][wrow] = wv.x; Ws[nxt][wko + 1][wrow] = wv.y;
            Ws[nxt][wko + 2][wrow] = wv.z; Ws[nxt][wko + 3][wrow] = wv.w;
            __syncthreads();
        }
    }

    float* out = (MODE == 0) ? g_hlin : outp;
#pragma unroll
    for (int i = 0; i < 4; ++i) {
        int r = bm + ty * 4 + i;
#pragma unroll
        for (int j = 0; j < 2; ++j) {
            int cc = bn + tx * 2 + j;
            float v = acc[i][j] + bias[cc];
            if (MODE == 1) v *= mul[r * 512 + cc];
            out[r * 512 + cc] = v;
        }
    }
}

// ---------------------------------------------------------------------------
// Kernel 2: scores[b,l,p] = sum_a relu(fmaps[b,p,a] + hlin[b,l,a]) * wrect[a]
// grid = (28 p-tiles of 7, 16 b) = 448 blocks (3/SM balanced), 256 threads.
// ---------------------------------------------------------------------------
__global__ __launch_bounds__(256) void scores_kernel(
    const float* __restrict__ fmaps, const float* __restrict__ wrect)
{
    const int b  = blockIdx.y;
    const int pt = blockIdx.x;           // 7-pixel tile
    __shared__ float4 fs4[PT * 128];     // 14 KB

    const float4* fbase = (const float4*)(fmaps + (size_t)(b * PP + pt * PT) * DD);
    for (int i = threadIdx.x; i < PT * 128; i += 256) fs4[i] = fbase[i];
    __syncthreads();

    const int w = threadIdx.x >> 5, lane = threadIdx.x & 31;
    float wr[4][4];
#pragma unroll
    for (int j = 0; j < 4; ++j) {
        float4 v = ((const float4*)wrect)[j * 32 + lane];
        wr[j][0] = v.x; wr[j][1] = v.y; wr[j][2] = v.z; wr[j][3] = v.w;
    }
#pragma unroll
    for (int lg = 0; lg < 4; ++lg) {
        const int l = lg * 8 + w;
        float g[4][4];
        const float4* gp = (const float4*)(g_hlin + (size_t)(b * LL + l) * AA);
#pragma unroll
        for (int j = 0; j < 4; ++j) {
            float4 v = gp[j * 32 + lane];
            g[j][0] = v.x; g[j][1] = v.y; g[j][2] = v.z; g[j][3] = v.w;
        }
#pragma unroll
        for (int p = 0; p < PT; ++p) {
            float acc = 0.f;
#pragma unroll
            for (int j = 0; j < 4; ++j) {
                float4 f = fs4[p * 128 + j * 32 + lane];
                acc = fmaf(fmaxf(f.x + g[j][0], 0.f), wr[j][0], acc);
                acc = fmaf(fmaxf(f.y + g[j][1], 0.f), wr[j][1], acc);
                acc = fmaf(fmaxf(f.z + g[j][2], 0.f), wr[j][2], acc);
                acc = fmaf(fmaxf(f.w + g[j][3], 0.f), wr[j][3], acc);
            }
#pragma unroll
            for (int o = 16; o; o >>= 1)
                acc += __shfl_xor_sync(0xffffffffu, acc, o);
            if (lane == 0)
                g_scores[(size_t)(b * LL + l) * PP + pt * PT + p] = acc;
        }
    }
}

// ---------------------------------------------------------------------------
// Kernel 3: softmax over P=196 per (b,l) row -> attnT [b][p][l] + d_out tail.
// ---------------------------------------------------------------------------
__global__ __launch_bounds__(256) void softmax_kernel(float* __restrict__ attn_out)
{
    const int row = blockIdx.x, tid = threadIdx.x;
    const int lane = tid & 31, wid = tid >> 5;
    const int b = row >> 5, l = row & 31;
    __shared__ float redm[8], reds[8];

    float v = -CUDART_INF_F;
    if (tid < PP) v = g_scores[(size_t)row * PP + tid];
    float m = v;
#pragma unroll
    for (int o = 16; o; o >>= 1) m = fmaxf(m, __shfl_xor_sync(0xffffffffu, m, o));
    if (lane == 0) redm[wid] = m;
    __syncthreads();
    float bm = redm[0];
#pragma unroll
    for (int i = 1; i < 8; ++i) bm = fmaxf(bm, redm[i]);

    float e = (tid < PP) ? __expf(v - bm) : 0.f;
    float s = e;
#pragma unroll
    for (int o = 16; o; o >>= 1) s += __shfl_xor_sync(0xffffffffu, s, o);
    if (lane == 0) reds[wid] = s;
    __syncthreads();
    float bs = 0.f;
#pragma unroll
    for (int i = 0; i < 8; ++i) bs += reds[i];
    float inv = 1.f / bs;

    if (tid < PP) {
        float a = e * inv;
        g_attnT[((size_t)b * PP + tid) * LL + l] = a;
        if (attn_out) attn_out[(size_t)row * PP + tid] = a;
    }
}

// ---------------------------------------------------------------------------
// Kernel 4: ctx[b] (32 x 512) = attn[b] (32 x 196) @ fmap[b] (196 x 512)
// grid = (8 d-tiles of 64, 16 b) = 128 blocks, 256 threads (16x16, TM=2, TN=4).
// KC=14 k-chunks x 14, double-buffered K-major smem, register prefetch.
// ---------------------------------------------------------------------------
__global__ __launch_bounds__(256) void ctx_gemm_kernel(const float* __restrict__ fmaps)
{
    __shared__ __align__(16) float As[2][KC][34];   // attnT chunk [k][l]
    __shared__ __align__(16) float Bs[2][KC][68];   // fmap chunk  [k][d]

    const int tid = threadIdx.x;
    const int tx = tid & 15;         // d: 4 each
    const int ty = tid >> 4;         // l: 2 each
    const int b  = blockIdx.y;
    const int dt = blockIdx.x * 64;

    const bool ld = tid < 224;
    const int brow = tid >> 4;                 // 0..13 (tid<224)
    const int bc4  = (tid & 15) * 4;
    const int ak   = (2 * tid) >> 5;           // 0..13
    const int al   = (2 * tid) & 31;           // even

    const float* bg = fmaps + (size_t)b * PP * 512 + dt + bc4;
    const float* ag = g_attnT + (size_t)b * PP * LL;

    float4 bv; float2 av;
    if (ld) {
        bv = *(const float4*)&bg[(size_t)brow * 512];
        av = *(const float2*)&ag[(size_t)ak * LL + al];
    }
    if (ld) {
        *(float4*)&Bs[0][brow][bc4] = bv;
        *(float2*)&As[0][ak][al] = av;
    }
    __syncthreads();

    float acc[2][4];
#pragma unroll
    for (int i = 0; i < 2; ++i)
#pragma unroll
        for (int j = 0; j < 4; ++j) acc[i][j] = 0.f;

#pragma unroll 1
    for (int c = 0; c < 14; ++c) {
        if (c < 13 && ld) {
            bv = *(const float4*)&bg[(size_t)((c + 1) * KC + brow) * 512];
            av = *(const float2*)&ag[(size_t)((c + 1) * KC + ak) * LL + al];
        }
        const int cur = c & 1;
#pragma unroll
        for (int k = 0; k < KC; ++k) {
            float2 a = *(const float2*)&As[cur][k][ty * 2];
            float4 bq = *(const float4*)&Bs[cur][k][tx * 4];
            acc[0][0] = fmaf(a.x, bq.x, acc[0][0]);
            acc[0][1] = fmaf(a.x, bq.y, acc[0][1]);
            acc[0][2] = fmaf(a.x, bq.z, acc[0][2]);
            acc[0][3] = fmaf(a.x, bq.w, acc[0][3]);
            acc[1][0] = fmaf(a.y, bq.x, acc[1][0]);
            acc[1][1] = fmaf(a.y, bq.y, acc[1][1]);
            acc[1][2] = fmaf(a.y, bq.z, acc[1][2]);
            acc[1][3] = fmaf(a.y, bq.w, acc[1][3]);
        }
        if (c < 13) {
            const int nxt = cur ^ 1;
            if (ld) {
                *(float4*)&Bs[nxt][brow][bc4] = bv;
                *(float2*)&As[nxt][ak][al] = av;
            }
            __syncthreads();
        }
    }

#pragma unroll
    for (int i = 0; i < 2; ++i) {
        const int l = ty * 2 + i;
        *(float4*)&g_ctx[((size_t)b * LL + l) * 512 + dt + tx * 4] =
            make_float4(acc[i][0], acc[i][1], acc[i][2], acc[i][3]);
    }
}

// ---------------------------------------------------------------------------
extern "C" void kernel_launch(void* const* d_in, const int* in_sizes, int n_in,
                              void* d_out, int out_size)
{
    const float* maps     = (const float*)d_in[0];
    const float* hiddens  = (const float*)d_in[1];
    const float* W_hidden = (const float*)d_in[2];
    const float* b_hidden = (const float*)d_in[3];
    const float* W_rect   = (const float*)d_in[4];
    // d_in[5] = b_rect: softmax-invariant, unused
    const float* W_co     = (const float*)d_in[6];
    const float* b_co     = (const float*)d_in[7];

    float* out_co = (float*)d_out;
    float* out_attn = nullptr;
    if (out_size >= MM * HID + MM * PP)
        out_attn = out_co + MM * HID;

    // 1) hlin = hiddens @ W_hidden^T + b_hidden   -> g_hlin
    gemm_nt_kernel<0><<<dim3(16, 8), 256>>>(hiddens, W_hidden, b_hidden,
                                            nullptr, nullptr);
    // 2) additive co-attention scores             -> g_scores
    scores_kernel<<<dim3(28, BB), 256>>>(maps, W_rect);
    // 3) softmax over pixels                      -> g_attnT (+ d_out tail)
    softmax_kernel<<<MM, 256>>>(out_attn);
    // 4) ctx = attn @ fmaps (per-batch GEMM)      -> g_ctx
    ctx_gemm_kernel<<<dim3(8, BB), 256>>>(maps);
    // 5) co_att = (ctx @ W_co^T + b_co) * hiddens -> d_out head
    gemm_nt_kernel<1><<<dim3(16, 8), 256>>>(nullptr, W_co, b_co,
                                            hiddens, out_co);
}